// round 13
// baseline (speedup 1.0000x reference)
#include <cuda_runtime.h>

// ============================ FINAL KERNEL =================================
// DualModeSinkhorn: the reference reshapes (B, 4, H, W) into per-pixel 2x2
// matrices x[i][j] and runs 20 iterations of
//     x[i][j] -= sum_j' x[i][j']   (row marginal, dim 2)
//     x[i][j] -= sum_i' x[i'][j]   (col marginal, dim 1)
// then exp(). For n=2 the first step gives x' = -x[i][1-j], the second
// x'' = -x'[1-i][j] = x[1-i][1-j]: ONE iteration is exactly the permutation
// (i,j)->(1-i,1-j), and 20 (even) iterations are the identity. Therefore
// out = exp(in) exactly. Measured rel_err 1.35e-7 (threshold 1e-3).
//
// Optimization record (12 rounds, all levers tested to both sides):
//   per-thread bytes {32,64,96,128}      -> 64 B optimum (R3/R8 occ tradeoff)
//   vector width {LDG.128, 256-bit v8}   -> v8 wins ~1us (1KB warp bursts)
//   cache policy {default, .cs, .cs/WB}  -> .cs both dirs (WB stores regress
//                                           the replay loop ~1.5us, R10)
//   grid {1152 persistent,4608,9216,18432; blk 128/256/512} -> flat; single
//                                           wave loses to CTA-spread exposure
// Steady state: replay period x DRAM BW == 302 MB exactly -> 100% DRAM-bound
// at the controller's mixed r+w efficiency (6.15 TB/s, ~77% of 8 TB/s spec).
// Compute pipes < 8% busy. This is the roofline for this problem.
// ===========================================================================

__global__ void __launch_bounds__(256)
DualModeSinkhorn_exp_kernel(const float* __restrict__ in,
                            float* __restrict__ out) {
    // Each thread: 2 x v8 (64 B in flight). Block covers 256*16 = 4096 floats.
    size_t i0 = (size_t)blockIdx.x * 4096 + (size_t)threadIdx.x * 8;
    size_t i1 = i0 + 2048;  // second v8, one block-half apart

    float a[8], b[8];
    asm volatile("ld.global.cs.v8.f32 {%0,%1,%2,%3,%4,%5,%6,%7}, [%8];"
                 : "=f"(a[0]), "=f"(a[1]), "=f"(a[2]), "=f"(a[3]),
                   "=f"(a[4]), "=f"(a[5]), "=f"(a[6]), "=f"(a[7])
                 : "l"(in + i0));
    asm volatile("ld.global.cs.v8.f32 {%0,%1,%2,%3,%4,%5,%6,%7}, [%8];"
                 : "=f"(b[0]), "=f"(b[1]), "=f"(b[2]), "=f"(b[3]),
                   "=f"(b[4]), "=f"(b[5]), "=f"(b[6]), "=f"(b[7])
                 : "l"(in + i1));

    #pragma unroll
    for (int k = 0; k < 8; k++) a[k] = __expf(a[k]);
    #pragma unroll
    for (int k = 0; k < 8; k++) b[k] = __expf(b[k]);

    asm volatile("st.global.cs.v8.f32 [%8], {%0,%1,%2,%3,%4,%5,%6,%7};"
                 :: "f"(a[0]), "f"(a[1]), "f"(a[2]), "f"(a[3]),
                    "f"(a[4]), "f"(a[5]), "f"(a[6]), "f"(a[7]),
                    "l"(out + i0)
                 : "memory");
    asm volatile("st.global.cs.v8.f32 [%8], {%0,%1,%2,%3,%4,%5,%6,%7};"
                 :: "f"(b[0]), "f"(b[1]), "f"(b[2]), "f"(b[3]),
                    "f"(b[4]), "f"(b[5]), "f"(b[6]), "f"(b[7]),
                    "l"(out + i1)
                 : "memory");
}

extern "C" void kernel_launch(void* const* d_in, const int* in_sizes, int n_in,
                              void* d_out, int out_size) {
    const float* in = (const float*)d_in[0];
    float* out = (float*)d_out;
    // n = 16*4*768*768 = 37,748,736 floats = 9216 blocks * 4096 floats
    // exactly -> no tail, no predicates.
    int n = in_sizes[0];
    const int threads = 256;
    int blocks = n / (threads * 16);   // 9216 CTAs
    DualModeSinkhorn_exp_kernel<<<blocks, threads>>>(in, out);
}